// round 1
// baseline (speedup 1.0000x reference)
#include <cuda_runtime.h>
#include <cuda_bf16.h>

// Problem constants
#define BB 4
#define LL 2048
#define EE 1024
#define HH 16
#define DD 64
#define MM (BB * LL)   // 8192 rows

// Scratch (allocation-free rule: __device__ globals)
__device__ float g_Q[MM * EE];
__device__ float g_K[MM * EE];
__device__ float g_V[MM * EE];
__device__ float g_O[MM * EE];

// ----------------------------------------------------------------------------
// Classic 128x128x8 register-blocked SGEMM. 256 threads, 8x8 per thread.
// C[M,N] = A[M,K] @ B[K,N] (+ bias[N] if bias != nullptr)
// ----------------------------------------------------------------------------
__global__ __launch_bounds__(256) void sgemm128(
    const float* __restrict__ A, const float* __restrict__ B,
    const float* __restrict__ bias, float* __restrict__ C,
    int M, int N, int K)
{
    __shared__ float As[8][128];   // transposed A tile: As[k][m]
    __shared__ float Bs[8][128];   // Bs[k][n]

    const int tid = threadIdx.x;
    const int m0 = blockIdx.y * 128;
    const int n0 = blockIdx.x * 128;
    const int ty = tid >> 4;       // 0..15 -> row group
    const int tx = tid & 15;       // 0..15 -> col group

    float acc[8][8];
    #pragma unroll
    for (int i = 0; i < 8; i++)
        #pragma unroll
        for (int j = 0; j < 8; j++) acc[i][j] = 0.0f;

    const int ar = tid >> 1;            // 0..127
    const int ac = (tid & 1) * 4;       // 0 or 4
    const int br = tid >> 5;            // 0..7
    const int bc = (tid & 31) * 4;      // 0..124

    const float* Aptr = A + (size_t)(m0 + ar) * K + ac;
    const float* Bptr = B + (size_t)br * N + n0 + bc;

    for (int kt = 0; kt < K; kt += 8) {
        float4 av = *(const float4*)(Aptr + kt);
        As[ac + 0][ar] = av.x;
        As[ac + 1][ar] = av.y;
        As[ac + 2][ar] = av.z;
        As[ac + 3][ar] = av.w;
        float4 bv = *(const float4*)(Bptr + (size_t)kt * N);
        *(float4*)&Bs[br][bc] = bv;
        __syncthreads();

        #pragma unroll
        for (int k = 0; k < 8; k++) {
            float a[8], b[8];
            *(float4*)(a)     = *(float4*)&As[k][ty * 8];
            *(float4*)(a + 4) = *(float4*)&As[k][ty * 8 + 4];
            *(float4*)(b)     = *(float4*)&Bs[k][tx * 8];
            *(float4*)(b + 4) = *(float4*)&Bs[k][tx * 8 + 4];
            #pragma unroll
            for (int i = 0; i < 8; i++)
                #pragma unroll
                for (int j = 0; j < 8; j++)
                    acc[i][j] = fmaf(a[i], b[j], acc[i][j]);
        }
        __syncthreads();
    }

    float bvals[8];
    #pragma unroll
    for (int j = 0; j < 8; j++)
        bvals[j] = bias ? bias[n0 + tx * 8 + j] : 0.0f;

    #pragma unroll
    for (int i = 0; i < 8; i++) {
        float* crow = C + (size_t)(m0 + ty * 8 + i) * N + n0 + tx * 8;
        float4 v0, v1;
        v0.x = acc[i][0] + bvals[0]; v0.y = acc[i][1] + bvals[1];
        v0.z = acc[i][2] + bvals[2]; v0.w = acc[i][3] + bvals[3];
        v1.x = acc[i][4] + bvals[4]; v1.y = acc[i][5] + bvals[5];
        v1.z = acc[i][6] + bvals[6]; v1.w = acc[i][7] + bvals[7];
        *(float4*)(crow)     = v0;
        *(float4*)(crow + 4) = v1;
    }
}

// ----------------------------------------------------------------------------
// Flash attention: per (b,h), 64-query tiles, online softmax over 64-key tiles.
// Q/K/V/O layout: [B, L, H, D] flattened (row stride E, head offset h*D).
// Softmax scale 1/sqrt(E) = 1/32 folded into Q load.
// ----------------------------------------------------------------------------
#define FPAD 65   // 64+1: kills the worst LDS bank conflicts (stride 4*65 % 32 = 4)

__global__ __launch_bounds__(256) void flash64(
    const float* __restrict__ Q, const float* __restrict__ Kg,
    const float* __restrict__ Vg, float* __restrict__ O)
{
    extern __shared__ float sm[];
    float* Qs = sm;                 // 64 x FPAD
    float* Ks = Qs + 64 * FPAD;
    float* Vs = Ks + 64 * FPAD;
    float* Ps = Vs + 64 * FPAD;

    const int tid = threadIdx.x;
    const int ty = tid >> 4;        // 0..15 -> query rows 4*ty..4*ty+3
    const int tx = tid & 15;        // 0..15 -> key cols / head dims 4*tx..4*tx+3
    const int q0 = blockIdx.x * 64;
    const int h  = blockIdx.y;
    const int b  = blockIdx.z;
    const float scale = 0.03125f;   // 1/sqrt(1024)

    const size_t base = (size_t)b * LL * EE + (size_t)h * DD;

    // Load Q tile (pre-scaled)
    {
        const int r = tid >> 2;
        const int c = (tid & 3) * 16;
        const float* src = Q + base + (size_t)(q0 + r) * EE + c;
        #pragma unroll
        for (int i = 0; i < 16; i++) Qs[r * FPAD + c + i] = src[i] * scale;
    }

    float m_i[4], l_i[4], o[4][4];
    #pragma unroll
    for (int i = 0; i < 4; i++) {
        m_i[i] = -1e30f; l_i[i] = 0.0f;
        #pragma unroll
        for (int j = 0; j < 4; j++) o[i][j] = 0.0f;
    }

    for (int kt = 0; kt < LL; kt += 64) {
        // Load K, V tiles
        {
            const int r = tid >> 2;
            const int c = (tid & 3) * 16;
            const float* ksrc = Kg + base + (size_t)(kt + r) * EE + c;
            const float* vsrc = Vg + base + (size_t)(kt + r) * EE + c;
            #pragma unroll
            for (int i = 0; i < 16; i++) Ks[r * FPAD + c + i] = ksrc[i];
            #pragma unroll
            for (int i = 0; i < 16; i++) Vs[r * FPAD + c + i] = vsrc[i];
        }
        __syncthreads();

        // S = Qs @ Ks^T (4x4 micro-tile)
        float s[4][4];
        #pragma unroll
        for (int i = 0; i < 4; i++)
            #pragma unroll
            for (int j = 0; j < 4; j++) s[i][j] = 0.0f;

        #pragma unroll 8
        for (int d = 0; d < 64; d++) {
            float qv[4], kv[4];
            #pragma unroll
            for (int i = 0; i < 4; i++) qv[i] = Qs[(4 * ty + i) * FPAD + d];
            #pragma unroll
            for (int j = 0; j < 4; j++) kv[j] = Ks[(4 * tx + j) * FPAD + d];
            #pragma unroll
            for (int i = 0; i < 4; i++)
                #pragma unroll
                for (int j = 0; j < 4; j++)
                    s[i][j] = fmaf(qv[i], kv[j], s[i][j]);
        }

        // Row max over the 16 tx lanes (tx = low 4 lane bits)
        float mt[4];
        #pragma unroll
        for (int i = 0; i < 4; i++) {
            mt[i] = fmaxf(fmaxf(s[i][0], s[i][1]), fmaxf(s[i][2], s[i][3]));
        }
        #pragma unroll
        for (int off = 1; off < 16; off <<= 1) {
            #pragma unroll
            for (int i = 0; i < 4; i++)
                mt[i] = fmaxf(mt[i], __shfl_xor_sync(0xffffffffu, mt[i], off));
        }

        float corr[4];
        #pragma unroll
        for (int i = 0; i < 4; i++) {
            float mn = fmaxf(m_i[i], mt[i]);
            corr[i] = __expf(m_i[i] - mn);
            m_i[i] = mn;
        }

        float p[4][4], ls[4];
        #pragma unroll
        for (int i = 0; i < 4; i++) {
            ls[i] = 0.0f;
            #pragma unroll
            for (int j = 0; j < 4; j++) {
                p[i][j] = __expf(s[i][j] - m_i[i]);
                ls[i] += p[i][j];
            }
        }
        #pragma unroll
        for (int off = 1; off < 16; off <<= 1) {
            #pragma unroll
            for (int i = 0; i < 4; i++)
                ls[i] += __shfl_xor_sync(0xffffffffu, ls[i], off);
        }
        #pragma unroll
        for (int i = 0; i < 4; i++) {
            l_i[i] = l_i[i] * corr[i] + ls[i];
            #pragma unroll
            for (int j = 0; j < 4; j++) o[i][j] *= corr[i];
        }

        // Stage P
        #pragma unroll
        for (int i = 0; i < 4; i++)
            #pragma unroll
            for (int j = 0; j < 4; j++)
                Ps[(4 * ty + i) * FPAD + 4 * tx + j] = p[i][j];
        __syncthreads();

        // O += P @ V
        #pragma unroll 4
        for (int jj = 0; jj < 64; jj++) {
            float pv[4], vv[4];
            #pragma unroll
            for (int i = 0; i < 4; i++) pv[i] = Ps[(4 * ty + i) * FPAD + jj];
            #pragma unroll
            for (int j = 0; j < 4; j++) vv[j] = Vs[jj * FPAD + 4 * tx + j];
            #pragma unroll
            for (int i = 0; i < 4; i++)
                #pragma unroll
                for (int j = 0; j < 4; j++)
                    o[i][j] = fmaf(pv[i], vv[j], o[i][j]);
        }
        __syncthreads();
    }

    // Write normalized output
    #pragma unroll
    for (int i = 0; i < 4; i++) {
        const float inv = 1.0f / l_i[i];
        float* dst = O + base + (size_t)(q0 + 4 * ty + i) * EE + 4 * tx;
        #pragma unroll
        for (int j = 0; j < 4; j++) dst[j] = o[i][j] * inv;
    }
}

// ----------------------------------------------------------------------------
extern "C" void kernel_launch(void* const* d_in, const int* in_sizes, int n_in,
                              void* d_out, int out_size)
{
    const float* x  = (const float*)d_in[0];
    const float* Wq = (const float*)d_in[1];
    const float* Wk = (const float*)d_in[2];
    const float* Wv = (const float*)d_in[3];
    const float* Wo = (const float*)d_in[4];
    const float* bo = (const float*)d_in[5];
    float* out = (float*)d_out;

    float *Qp, *Kp, *Vp, *Op;
    cudaGetSymbolAddress((void**)&Qp, g_Q);
    cudaGetSymbolAddress((void**)&Kp, g_K);
    cudaGetSymbolAddress((void**)&Vp, g_V);
    cudaGetSymbolAddress((void**)&Op, g_O);

    dim3 gg(EE / 128, MM / 128);   // (8, 64)

    // Projections
    sgemm128<<<gg, 256>>>(x, Wq, nullptr, Qp, MM, EE, EE);
    sgemm128<<<gg, 256>>>(x, Wk, nullptr, Kp, MM, EE, EE);
    sgemm128<<<gg, 256>>>(x, Wv, nullptr, Vp, MM, EE, EE);

    // Attention
    size_t smem = 4 * 64 * FPAD * sizeof(float);   // 66,560 B
    cudaFuncSetAttribute(flash64, cudaFuncAttributeMaxDynamicSharedMemorySize,
                         (int)smem);
    dim3 ga(LL / 64, HH, BB);      // (32, 16, 4)
    flash64<<<ga, 256, smem>>>(Qp, Kp, Vp, Op);

    // Output projection + bias
    sgemm128<<<gg, 256>>>(Op, Wo, bo, out, MM, EE, EE);
}

// round 2
// speedup vs baseline: 1.3278x; 1.3278x over previous
#include <cuda_runtime.h>
#include <cuda_bf16.h>
#include <cstdint>

// Problem constants
#define BB 4
#define LL 2048
#define EE 1024
#define HH 16
#define DD 64
#define MM (BB * LL)   // 8192 rows

// Scratch (allocation-free rule: __device__ globals)
__device__ float g_Q[MM * EE];
__device__ float g_K[MM * EE];
__device__ float g_V[MM * EE];
__device__ float g_O[MM * EE];

// ----------------------------------------------------------------------------
// tf32 helpers
// ----------------------------------------------------------------------------
__device__ __forceinline__ uint32_t f2tf32(float a) {
    uint32_t r;
    asm("cvt.rna.tf32.f32 %0, %1;" : "=r"(r) : "f"(a));
    return r;
}

__device__ __forceinline__ void mma_tf32_m16n8k8(
    float d[4], uint32_t a0, uint32_t a1, uint32_t a2, uint32_t a3,
    uint32_t b0, uint32_t b1)
{
    asm volatile(
        "mma.sync.aligned.m16n8k8.row.col.f32.tf32.tf32.f32 "
        "{%0,%1,%2,%3}, {%4,%5,%6,%7}, {%8,%9}, {%0,%1,%2,%3};"
        : "+f"(d[0]), "+f"(d[1]), "+f"(d[2]), "+f"(d[3])
        : "r"(a0), "r"(a1), "r"(a2), "r"(a3), "r"(b0), "r"(b1));
}

// ----------------------------------------------------------------------------
// tf32x3 GEMM: C[M,N] = A[M,K] @ B[K,N] (+bias). Block 128x128, BK=32.
// 256 threads = 8 warps (2 m x 4 n), warp tile 64x32, mma m16n8k8.
// A and B split into tf32 hi/lo in smem; 3 MMA products (hi*hi, hi*lo, lo*hi).
// ----------------------------------------------------------------------------
#define GLD 132   // smem row stride (128 + 4 pad), k-major rows

__global__ __launch_bounds__(256) void gemm_tf32x3(
    const float* __restrict__ A, const float* __restrict__ B,
    const float* __restrict__ bias, float* __restrict__ C,
    int M, int N, int K)
{
    extern __shared__ float gsm[];
    float* AsH = gsm;                 // [32][GLD]  (k-major, m index inside row)
    float* AsL = AsH + 32 * GLD;
    float* BsH = AsL + 32 * GLD;      // [32][GLD]  (k-major, n index inside row)
    float* BsL = BsH + 32 * GLD;

    const int tid  = threadIdx.x;
    const int lane = tid & 31;
    const int wid  = tid >> 5;
    const int wm   = (wid >> 2) * 64;    // warp m offset in tile
    const int wn   = (wid & 3) * 32;     // warp n offset in tile
    const int g    = lane >> 2;          // group id 0..7
    const int t    = lane & 3;           // thread in group 0..3

    const int m0 = blockIdx.y * 128;
    const int n0 = blockIdx.x * 128;

    float acc[4][4][4];
    #pragma unroll
    for (int i = 0; i < 4; i++)
        #pragma unroll
        for (int j = 0; j < 4; j++)
            #pragma unroll
            for (int r = 0; r < 4; r++) acc[i][j][r] = 0.0f;

    // gmem load indices
    const int ar  = tid >> 1;            // 0..127 (A row within tile)
    const int ac4 = (tid & 1) * 16;      // A col start (0 or 16)
    const int br  = tid >> 3;            // 0..31 (B row = k)
    const int bc  = (tid & 7) * 16;      // B col start

    for (int k0 = 0; k0 < K; k0 += 32) {
        // ---- A tile: load fp32, split hi/lo, store transposed [k][m] ----
        {
            const float* ap = A + (size_t)(m0 + ar) * K + k0 + ac4;
            #pragma unroll
            for (int u = 0; u < 4; u++) {
                float4 v = *(const float4*)(ap + u * 4);
                float vv[4] = {v.x, v.y, v.z, v.w};
                #pragma unroll
                for (int e = 0; e < 4; e++) {
                    uint32_t hi = f2tf32(vv[e]);
                    float lo = vv[e] - __uint_as_float(hi);
                    uint32_t lot = f2tf32(lo);
                    int kk = ac4 + u * 4 + e;
                    AsH[kk * GLD + ar] = __uint_as_float(hi);
                    AsL[kk * GLD + ar] = __uint_as_float(lot);
                }
            }
        }
        // ---- B tile: load fp32, split hi/lo, store [k][n] ----
        {
            const float* bp = B + (size_t)(k0 + br) * N + n0 + bc;
            #pragma unroll
            for (int u = 0; u < 4; u++) {
                float4 v = *(const float4*)(bp + u * 4);
                float vv[4] = {v.x, v.y, v.z, v.w};
                float hi4[4], lo4[4];
                #pragma unroll
                for (int e = 0; e < 4; e++) {
                    uint32_t hi = f2tf32(vv[e]);
                    float lo = vv[e] - __uint_as_float(hi);
                    hi4[e] = __uint_as_float(hi);
                    lo4[e] = __uint_as_float(f2tf32(lo));
                }
                *(float4*)&BsH[br * GLD + bc + u * 4] = make_float4(hi4[0], hi4[1], hi4[2], hi4[3]);
                *(float4*)&BsL[br * GLD + bc + u * 4] = make_float4(lo4[0], lo4[1], lo4[2], lo4[3]);
            }
        }
        __syncthreads();

        #pragma unroll
        for (int ks = 0; ks < 4; ks++) {
            const int k8 = ks * 8;
            // A fragments (hi & lo) for 4 m-tiles
            uint32_t ah[4][4], al[4][4];
            #pragma unroll
            for (int mt = 0; mt < 4; mt++) {
                const int mb = wm + mt * 16;
                const int r0 = (k8 + t) * GLD + mb + g;
                const int r1 = (k8 + t + 4) * GLD + mb + g;
                ah[mt][0] = __float_as_uint(AsH[r0]);
                ah[mt][1] = __float_as_uint(AsH[r0 + 8]);
                ah[mt][2] = __float_as_uint(AsH[r1]);
                ah[mt][3] = __float_as_uint(AsH[r1 + 8]);
                al[mt][0] = __float_as_uint(AsL[r0]);
                al[mt][1] = __float_as_uint(AsL[r0 + 8]);
                al[mt][2] = __float_as_uint(AsL[r1]);
                al[mt][3] = __float_as_uint(AsL[r1 + 8]);
            }
            // B fragments (hi & lo) for 4 n-tiles
            uint32_t bh[4][2], bl[4][2];
            #pragma unroll
            for (int nt = 0; nt < 4; nt++) {
                const int nb = wn + nt * 8;
                const int r0 = (k8 + t) * GLD + nb + g;
                const int r1 = (k8 + t + 4) * GLD + nb + g;
                bh[nt][0] = __float_as_uint(BsH[r0]);
                bh[nt][1] = __float_as_uint(BsH[r1]);
                bl[nt][0] = __float_as_uint(BsL[r0]);
                bl[nt][1] = __float_as_uint(BsL[r1]);
            }
            #pragma unroll
            for (int mt = 0; mt < 4; mt++)
                #pragma unroll
                for (int nt = 0; nt < 4; nt++) {
                    mma_tf32_m16n8k8(acc[mt][nt], al[mt][0], al[mt][1], al[mt][2], al[mt][3],
                                     bh[nt][0], bh[nt][1]);
                    mma_tf32_m16n8k8(acc[mt][nt], ah[mt][0], ah[mt][1], ah[mt][2], ah[mt][3],
                                     bl[nt][0], bl[nt][1]);
                    mma_tf32_m16n8k8(acc[mt][nt], ah[mt][0], ah[mt][1], ah[mt][2], ah[mt][3],
                                     bh[nt][0], bh[nt][1]);
                }
        }
        __syncthreads();
    }

    // Epilogue
    #pragma unroll
    for (int mt = 0; mt < 4; mt++) {
        const int r0 = m0 + wm + mt * 16 + g;
        #pragma unroll
        for (int nt = 0; nt < 4; nt++) {
            const int c = n0 + wn + nt * 8 + 2 * t;
            float b0 = bias ? bias[c]     : 0.0f;
            float b1 = bias ? bias[c + 1] : 0.0f;
            *(float2*)&C[(size_t)r0 * N + c] =
                make_float2(acc[mt][nt][0] + b0, acc[mt][nt][1] + b1);
            *(float2*)&C[(size_t)(r0 + 8) * N + c] =
                make_float2(acc[mt][nt][2] + b0, acc[mt][nt][3] + b1);
        }
    }
}

// ----------------------------------------------------------------------------
// Flash attention v2: 128 q-rows per block, 64-key tiles, online softmax.
// Q/K stored d-major (transposed) in smem so inner-loop reads are float4
// conflict-free or broadcasts. 8x4 per-thread micro-tile.
// ----------------------------------------------------------------------------
#define QLD 132   // Qt row stride: 128 + 4
#define SLD 68    // K/V/P row stride: 64 + 4

__global__ __launch_bounds__(256) void flash128(
    const float* __restrict__ Q, const float* __restrict__ Kg,
    const float* __restrict__ Vg, float* __restrict__ O)
{
    extern __shared__ float sm[];
    float* Qt = sm;                    // [64 d][QLD]   (Qt[d][q])
    float* Kt = Qt + 64 * QLD;         // [64 d][SLD]   (Kt[d][k])
    float* Vs = Kt + 64 * SLD;         // [64 k][SLD]   (Vs[k][d])
    float* Ps = Vs + 64 * SLD;         // [128 q][SLD]  (Ps[q][k])

    const int tid = threadIdx.x;
    const int ty = tid >> 4;           // 0..15 -> q rows 8ty..8ty+7
    const int tx = tid & 15;           // 0..15 -> cols 4tx..4tx+3
    const int q0 = blockIdx.x * 128;
    const int h  = blockIdx.y;
    const int b  = blockIdx.z;
    const float scale = 0.03125f;      // 1/sqrt(1024)

    const size_t base = (size_t)b * LL * EE + (size_t)h * DD;

    // Load Q tile (pre-scaled), transpose to d-major
    {
        const int r  = tid >> 1;             // 0..127
        const int d0 = (tid & 1) * 32;       // 0 or 32
        const float* src = Q + base + (size_t)(q0 + r) * EE + d0;
        #pragma unroll
        for (int u = 0; u < 8; u++) {
            float4 v = *(const float4*)(src + u * 4);
            Qt[(d0 + u * 4 + 0) * QLD + r] = v.x * scale;
            Qt[(d0 + u * 4 + 1) * QLD + r] = v.y * scale;
            Qt[(d0 + u * 4 + 2) * QLD + r] = v.z * scale;
            Qt[(d0 + u * 4 + 3) * QLD + r] = v.w * scale;
        }
    }

    float m_i[8], l_i[8], o[8][4];
    #pragma unroll
    for (int i = 0; i < 8; i++) {
        m_i[i] = -1e30f; l_i[i] = 0.0f;
        #pragma unroll
        for (int j = 0; j < 4; j++) o[i][j] = 0.0f;
    }

    for (int kt = 0; kt < LL; kt += 64) {
        __syncthreads();   // previous PV done before overwriting K/V
        // Load K (transposed) and V tiles
        {
            const int r  = tid >> 2;          // 0..63
            const int c0 = (tid & 3) * 16;    // 0,16,32,48
            const float* ksrc = Kg + base + (size_t)(kt + r) * EE + c0;
            const float* vsrc = Vg + base + (size_t)(kt + r) * EE + c0;
            #pragma unroll
            for (int u = 0; u < 4; u++) {
                float4 kv = *(const float4*)(ksrc + u * 4);
                Kt[(c0 + u * 4 + 0) * SLD + r] = kv.x;
                Kt[(c0 + u * 4 + 1) * SLD + r] = kv.y;
                Kt[(c0 + u * 4 + 2) * SLD + r] = kv.z;
                Kt[(c0 + u * 4 + 3) * SLD + r] = kv.w;
            }
            #pragma unroll
            for (int u = 0; u < 4; u++) {
                float4 vv = *(const float4*)(vsrc + u * 4);
                *(float4*)&Vs[r * SLD + c0 + u * 4] = vv;
            }
        }
        __syncthreads();

        // S = Q @ K^T : s[8][4]
        float s[8][4];
        #pragma unroll
        for (int i = 0; i < 8; i++)
            #pragma unroll
            for (int j = 0; j < 4; j++) s[i][j] = 0.0f;

        #pragma unroll 4
        for (int d = 0; d < 64; d++) {
            float4 qa = *(float4*)&Qt[d * QLD + 8 * ty];
            float4 qb = *(float4*)&Qt[d * QLD + 8 * ty + 4];
            float4 kv = *(float4*)&Kt[d * SLD + 4 * tx];
            float qv[8] = {qa.x, qa.y, qa.z, qa.w, qb.x, qb.y, qb.z, qb.w};
            float kk[4] = {kv.x, kv.y, kv.z, kv.w};
            #pragma unroll
            for (int i = 0; i < 8; i++)
                #pragma unroll
                for (int j = 0; j < 4; j++)
                    s[i][j] = fmaf(qv[i], kk[j], s[i][j]);
        }

        // Row max across the 16 tx lanes
        float mt[8];
        #pragma unroll
        for (int i = 0; i < 8; i++)
            mt[i] = fmaxf(fmaxf(s[i][0], s[i][1]), fmaxf(s[i][2], s[i][3]));
        #pragma unroll
        for (int off = 1; off < 16; off <<= 1)
            #pragma unroll
            for (int i = 0; i < 8; i++)
                mt[i] = fmaxf(mt[i], __shfl_xor_sync(0xffffffffu, mt[i], off));

        float corr[8];
        #pragma unroll
        for (int i = 0; i < 8; i++) {
            float mn = fmaxf(m_i[i], mt[i]);
            corr[i] = __expf(m_i[i] - mn);
            m_i[i] = mn;
        }

        float ls[8];
        #pragma unroll
        for (int i = 0; i < 8; i++) {
            ls[i] = 0.0f;
            #pragma unroll
            for (int j = 0; j < 4; j++) {
                s[i][j] = __expf(s[i][j] - m_i[i]);
                ls[i] += s[i][j];
            }
        }
        #pragma unroll
        for (int off = 1; off < 16; off <<= 1)
            #pragma unroll
            for (int i = 0; i < 8; i++)
                ls[i] += __shfl_xor_sync(0xffffffffu, ls[i], off);
        #pragma unroll
        for (int i = 0; i < 8; i++) {
            l_i[i] = l_i[i] * corr[i] + ls[i];
            #pragma unroll
            for (int j = 0; j < 4; j++) o[i][j] *= corr[i];
        }

        // Stage P (float4 stores, conflict-free)
        #pragma unroll
        for (int i = 0; i < 8; i++)
            *(float4*)&Ps[(8 * ty + i) * SLD + 4 * tx] =
                make_float4(s[i][0], s[i][1], s[i][2], s[i][3]);
        __syncthreads();

        // O += P @ V
        #pragma unroll 4
        for (int jj = 0; jj < 64; jj++) {
            float4 vv4 = *(float4*)&Vs[jj * SLD + 4 * tx];
            float vv[4] = {vv4.x, vv4.y, vv4.z, vv4.w};
            #pragma unroll
            for (int i = 0; i < 8; i++) {
                float pv = Ps[(8 * ty + i) * SLD + jj];
                #pragma unroll
                for (int j = 0; j < 4; j++)
                    o[i][j] = fmaf(pv, vv[j], o[i][j]);
            }
        }
    }

    // Write normalized output
    #pragma unroll
    for (int i = 0; i < 8; i++) {
        const float inv = 1.0f / l_i[i];
        float* dst = O + base + (size_t)(q0 + 8 * ty + i) * EE + 4 * tx;
        *(float4*)dst = make_float4(o[i][0] * inv, o[i][1] * inv,
                                    o[i][2] * inv, o[i][3] * inv);
    }
}

// ----------------------------------------------------------------------------
extern "C" void kernel_launch(void* const* d_in, const int* in_sizes, int n_in,
                              void* d_out, int out_size)
{
    const float* x  = (const float*)d_in[0];
    const float* Wq = (const float*)d_in[1];
    const float* Wk = (const float*)d_in[2];
    const float* Wv = (const float*)d_in[3];
    const float* Wo = (const float*)d_in[4];
    const float* bo = (const float*)d_in[5];
    float* out = (float*)d_out;

    float *Qp, *Kp, *Vp, *Op;
    cudaGetSymbolAddress((void**)&Qp, g_Q);
    cudaGetSymbolAddress((void**)&Kp, g_K);
    cudaGetSymbolAddress((void**)&Vp, g_V);
    cudaGetSymbolAddress((void**)&Op, g_O);

    // GEMM config
    size_t gsmem = 4 * 32 * GLD * sizeof(float);   // 67,584 B
    cudaFuncSetAttribute(gemm_tf32x3, cudaFuncAttributeMaxDynamicSharedMemorySize,
                         (int)gsmem);
    dim3 gg(EE / 128, MM / 128);   // (8, 64)

    // Projections (tf32x3 tensor cores)
    gemm_tf32x3<<<gg, 256, gsmem>>>(x, Wq, nullptr, Qp, MM, EE, EE);
    gemm_tf32x3<<<gg, 256, gsmem>>>(x, Wk, nullptr, Kp, MM, EE, EE);
    gemm_tf32x3<<<gg, 256, gsmem>>>(x, Wv, nullptr, Vp, MM, EE, EE);

    // Attention
    size_t fsmem = (64 * QLD + 64 * SLD + 64 * SLD + 128 * SLD) * sizeof(float);
    cudaFuncSetAttribute(flash128, cudaFuncAttributeMaxDynamicSharedMemorySize,
                         (int)fsmem);
    dim3 ga(LL / 128, HH, BB);     // (16, 16, 4)
    flash128<<<ga, 256, fsmem>>>(Qp, Kp, Vp, Op);

    // Output projection + bias (tensor cores)
    gemm_tf32x3<<<gg, 256, gsmem>>>(Op, Wo, bo, out, MM, EE, EE);
}

// round 4
// speedup vs baseline: 2.4239x; 1.8255x over previous
#include <cuda_runtime.h>
#include <cuda_bf16.h>
#include <cstdint>

// Problem constants
#define BB 4
#define LL 2048
#define EE 1024
#define HH 16
#define DD 64
#define MM (BB * LL)   // 8192 rows

// Scratch (allocation-free rule: __device__ globals)
__device__ float g_Q[MM * EE];
__device__ float g_K[MM * EE];
__device__ float g_V[MM * EE];
__device__ float g_O[MM * EE];
__device__ float g_Ah[MM * EE];
__device__ float g_Al[MM * EE];
__device__ float g_Wh[EE * EE];
__device__ float g_Wl[EE * EE];

// ----------------------------------------------------------------------------
// tf32 + cp.async helpers
// ----------------------------------------------------------------------------
__device__ __forceinline__ uint32_t f2tf32(float a) {
    uint32_t r;
    asm("cvt.rna.tf32.f32 %0, %1;" : "=r"(r) : "f"(a));
    return r;
}
__device__ __forceinline__ float f2tf32f(float a) {
    return __uint_as_float(f2tf32(a));
}

__device__ __forceinline__ void mma_tf32_m16n8k8(
    float d[4], uint32_t a0, uint32_t a1, uint32_t a2, uint32_t a3,
    uint32_t b0, uint32_t b1)
{
    asm volatile(
        "mma.sync.aligned.m16n8k8.row.col.f32.tf32.tf32.f32 "
        "{%0,%1,%2,%3}, {%4,%5,%6,%7}, {%8,%9}, {%0,%1,%2,%3};"
        : "+f"(d[0]), "+f"(d[1]), "+f"(d[2]), "+f"(d[3])
        : "r"(a0), "r"(a1), "r"(a2), "r"(a3), "r"(b0), "r"(b1));
}

__device__ __forceinline__ void cp16(uint32_t smem_dst, const void* gsrc) {
    asm volatile("cp.async.cg.shared.global [%0], [%1], 16;\n"
                 :: "r"(smem_dst), "l"(gsrc));
}
__device__ __forceinline__ void cp_commit() {
    asm volatile("cp.async.commit_group;\n");
}
template <int N> __device__ __forceinline__ void cp_wait() {
    asm volatile("cp.async.wait_group %0;\n" :: "n"(N));
}

// ----------------------------------------------------------------------------
// Split fp32 -> (tf32-hi, tf32-lo) elementwise. n4 = element count / 4.
// ----------------------------------------------------------------------------
__global__ __launch_bounds__(256) void split_tf32(
    const float4* __restrict__ in, float4* __restrict__ hi,
    float4* __restrict__ lo, int n4)
{
    int i = blockIdx.x * blockDim.x + threadIdx.x;
    if (i >= n4) return;
    float4 v = in[i];
    float4 h, l;
    h.x = f2tf32f(v.x); l.x = f2tf32f(v.x - h.x);
    h.y = f2tf32f(v.y); l.y = f2tf32f(v.y - h.y);
    h.z = f2tf32f(v.z); l.z = f2tf32f(v.z - h.z);
    h.w = f2tf32f(v.w); l.w = f2tf32f(v.w - h.w);
    hi[i] = h;
    lo[i] = l;
}

// ----------------------------------------------------------------------------
// tf32x3 GEMM with pre-split operands + 2-stage cp.async pipeline.
// C[M,N] = (Ah+Al)[M,K] @ (Bh+Bl)[K,N] (+bias). Block 128x128, BK=32.
// 256 threads = 8 warps (2m x 4n), warp tile 64x32, mma m16n8k8.
// ----------------------------------------------------------------------------
#define ALD 36     // A smem row stride (m-major, 32 + 4 pad)
#define BLD 136    // B smem row stride (k-major, 128 + 8 pad)
#define STAGE_F (2 * 128 * ALD + 2 * 32 * BLD)   // floats per stage = 17920

__global__ __launch_bounds__(256, 1) void gemm_tf32x3(
    const float* __restrict__ Ah, const float* __restrict__ Al,
    const float* __restrict__ Bh, const float* __restrict__ Bl,
    const float* __restrict__ bias, float* __restrict__ C,
    int M, int N, int K)
{
    extern __shared__ float gsm[];
    const uint32_t smbase = (uint32_t)__cvta_generic_to_shared(gsm);

    const int tid  = threadIdx.x;
    const int lane = tid & 31;
    const int wid  = tid >> 5;
    const int wm   = (wid >> 2) * 64;
    const int wn   = (wid & 3) * 32;
    const int g    = lane >> 2;
    const int t    = lane & 3;

    const int m0 = blockIdx.y * 128;
    const int n0 = blockIdx.x * 128;

    float acc[4][4][4];
    #pragma unroll
    for (int i = 0; i < 4; i++)
        #pragma unroll
        for (int j = 0; j < 4; j++)
            #pragma unroll
            for (int r = 0; r < 4; r++) acc[i][j][r] = 0.0f;

    // load indices
    const int arr = tid >> 3;            // 0..31 base row for A (4 passes of 32)
    const int arc = (tid & 7) * 4;       // A col
    const int brr = tid >> 5;            // 0..7 base row for B (4 passes of 8)
    const int brc = (tid & 31) * 4;      // B col

    auto load_stage = [&](int stage, int k0) {
        const uint32_t s0 = smbase + stage * STAGE_F * 4;
        const uint32_t aH = s0;
        const uint32_t aL = s0 + 128 * ALD * 4;
        const uint32_t bH = s0 + 2 * 128 * ALD * 4;
        const uint32_t bL = bH + 32 * BLD * 4;
        #pragma unroll
        for (int p = 0; p < 4; p++) {
            const int r = arr + p * 32;
            const size_t go = (size_t)(m0 + r) * K + k0 + arc;
            const uint32_t so = (r * ALD + arc) * 4;
            cp16(aH + so, Ah + go);
            cp16(aL + so, Al + go);
        }
        #pragma unroll
        for (int p = 0; p < 4; p++) {
            const int r = brr + p * 8;
            const size_t go = (size_t)(k0 + r) * N + n0 + brc;
            const uint32_t so = (r * BLD + brc) * 4;
            cp16(bH + so, Bh + go);
            cp16(bL + so, Bl + go);
        }
        cp_commit();
    };

    load_stage(0, 0);

    const int ntiles = K / 32;
    for (int kt = 0; kt < ntiles; kt++) {
        if (kt + 1 < ntiles) {
            load_stage((kt + 1) & 1, (kt + 1) * 32);
            cp_wait<1>();
        } else {
            cp_wait<0>();
        }
        __syncthreads();

        const float* AsH = gsm + (kt & 1) * STAGE_F;
        const float* AsL = AsH + 128 * ALD;
        const float* BsH = AsL + 128 * ALD;
        const float* BsL = BsH + 32 * BLD;

        #pragma unroll
        for (int ks = 0; ks < 4; ks++) {
            const int k8 = ks * 8;
            uint32_t ah[4][4], al[4][4];
            #pragma unroll
            for (int mt = 0; mt < 4; mt++) {
                const int ra = (wm + mt * 16 + g) * ALD + k8 + t;
                ah[mt][0] = __float_as_uint(AsH[ra]);
                ah[mt][1] = __float_as_uint(AsH[ra + 8 * ALD]);
                ah[mt][2] = __float_as_uint(AsH[ra + 4]);
                ah[mt][3] = __float_as_uint(AsH[ra + 8 * ALD + 4]);
                al[mt][0] = __float_as_uint(AsL[ra]);
                al[mt][1] = __float_as_uint(AsL[ra + 8 * ALD]);
                al[mt][2] = __float_as_uint(AsL[ra + 4]);
                al[mt][3] = __float_as_uint(AsL[ra + 8 * ALD + 4]);
            }
            uint32_t bh[4][2], bl[4][2];
            #pragma unroll
            for (int nt = 0; nt < 4; nt++) {
                const int rb = (k8 + t) * BLD + wn + nt * 8 + g;
                bh[nt][0] = __float_as_uint(BsH[rb]);
                bh[nt][1] = __float_as_uint(BsH[rb + 4 * BLD]);
                bl[nt][0] = __float_as_uint(BsL[rb]);
                bl[nt][1] = __float_as_uint(BsL[rb + 4 * BLD]);
            }
            #pragma unroll
            for (int mt = 0; mt < 4; mt++)
                #pragma unroll
                for (int nt = 0; nt < 4; nt++) {
                    mma_tf32_m16n8k8(acc[mt][nt], al[mt][0], al[mt][1], al[mt][2], al[mt][3],
                                     bh[nt][0], bh[nt][1]);
                    mma_tf32_m16n8k8(acc[mt][nt], ah[mt][0], ah[mt][1], ah[mt][2], ah[mt][3],
                                     bl[nt][0], bl[nt][1]);
                    mma_tf32_m16n8k8(acc[mt][nt], ah[mt][0], ah[mt][1], ah[mt][2], ah[mt][3],
                                     bh[nt][0], bh[nt][1]);
                }
        }
        __syncthreads();
    }

    // Epilogue
    #pragma unroll
    for (int mt = 0; mt < 4; mt++) {
        const int r0 = m0 + wm + mt * 16 + g;
        #pragma unroll
        for (int nt = 0; nt < 4; nt++) {
            const int c = n0 + wn + nt * 8 + 2 * t;
            float b0 = bias ? bias[c]     : 0.0f;
            float b1 = bias ? bias[c + 1] : 0.0f;
            *(float2*)&C[(size_t)r0 * N + c] =
                make_float2(acc[mt][nt][0] + b0, acc[mt][nt][1] + b1);
            *(float2*)&C[(size_t)(r0 + 8) * N + c] =
                make_float2(acc[mt][nt][2] + b0, acc[mt][nt][3] + b1);
        }
    }
}

// ----------------------------------------------------------------------------
// Flash attention with tf32 tensor-core MMAs.
// 128 q-rows/block, 64-key tiles; 8 warps, each owns 16 q-rows (m16).
// S = Q@K^T via m16n8k8 (k = d, 8 steps; n = keys, 8 tiles);
// softmax in C-fragments; P staged to smem; O += P@V via m16n8k8.
// ----------------------------------------------------------------------------
#define FQLD 68   // Qs row stride (q-major)
#define FKLD 68   // Ks row stride (key-major)
#define FVLD 72   // Vs row stride (key-major)
#define FPLD 72   // Ps row stride (q-major)

__global__ __launch_bounds__(256, 1) void flash_mma(
    const float* __restrict__ Q, const float* __restrict__ Kg,
    const float* __restrict__ Vg, float* __restrict__ O)
{
    extern __shared__ float sm[];
    float* Qs = sm;                       // [128][FQLD]
    float* Ks = Qs + 128 * FQLD;          // [64][FKLD]
    float* Vs = Ks + 64 * FKLD;           // [64][FVLD]
    float* Ps = Vs + 64 * FVLD;           // [128][FPLD]

    const int tid  = threadIdx.x;
    const int lane = tid & 31;
    const int wid  = tid >> 5;
    const int g    = lane >> 2;
    const int t    = lane & 3;
    const int qw   = wid * 16;            // warp's q-row offset in tile

    const int q0 = blockIdx.x * 128;
    const int h  = blockIdx.y;
    const int b  = blockIdx.z;
    const float scale = 0.03125f;         // 1/sqrt(1024)
    const size_t base = (size_t)b * LL * EE + (size_t)h * DD;

    // Load Q tile (scale + tf32 round), q-major
    {
        const int r  = tid >> 1;              // 0..127
        const int c0 = (tid & 1) * 32;        // 0 or 32
        const float* src = Q + base + (size_t)(q0 + r) * EE + c0;
        #pragma unroll
        for (int u = 0; u < 8; u++) {
            float4 v = *(const float4*)(src + u * 4);
            Qs[r * FQLD + c0 + u * 4 + 0] = f2tf32f(v.x * scale);
            Qs[r * FQLD + c0 + u * 4 + 1] = f2tf32f(v.y * scale);
            Qs[r * FQLD + c0 + u * 4 + 2] = f2tf32f(v.z * scale);
            Qs[r * FQLD + c0 + u * 4 + 3] = f2tf32f(v.w * scale);
        }
    }

    float m_i[2] = {-1e30f, -1e30f};
    float l_i[2] = {0.0f, 0.0f};
    float o[8][4];
    #pragma unroll
    for (int nt = 0; nt < 8; nt++)
        #pragma unroll
        for (int r = 0; r < 4; r++) o[nt][r] = 0.0f;

    for (int kt = 0; kt < LL; kt += 64) {
        __syncthreads();   // prior PV reads of Ks/Vs done before overwrite
        // Load K, V tiles (tf32 round), key-major
        {
            const int r  = tid >> 2;           // 0..63
            const int c0 = (tid & 3) * 16;     // 0,16,32,48
            const float* ksrc = Kg + base + (size_t)(kt + r) * EE + c0;
            const float* vsrc = Vg + base + (size_t)(kt + r) * EE + c0;
            #pragma unroll
            for (int u = 0; u < 4; u++) {
                float4 v = *(const float4*)(ksrc + u * 4);
                Ks[r * FKLD + c0 + u * 4 + 0] = f2tf32f(v.x);
                Ks[r * FKLD + c0 + u * 4 + 1] = f2tf32f(v.y);
                Ks[r * FKLD + c0 + u * 4 + 2] = f2tf32f(v.z);
                Ks[r * FKLD + c0 + u * 4 + 3] = f2tf32f(v.w);
            }
            #pragma unroll
            for (int u = 0; u < 4; u++) {
                float4 v = *(const float4*)(vsrc + u * 4);
                Vs[r * FVLD + c0 + u * 4 + 0] = f2tf32f(v.x);
                Vs[r * FVLD + c0 + u * 4 + 1] = f2tf32f(v.y);
                Vs[r * FVLD + c0 + u * 4 + 2] = f2tf32f(v.z);
                Vs[r * FVLD + c0 + u * 4 + 3] = f2tf32f(v.w);
            }
        }
        __syncthreads();

        // S = Q @ K^T : 8 n-tiles (keys), 8 k-steps (d)
        float s[8][4];
        #pragma unroll
        for (int nt = 0; nt < 8; nt++)
            #pragma unroll
            for (int r = 0; r < 4; r++) s[nt][r] = 0.0f;

        #pragma unroll
        for (int ks = 0; ks < 8; ks++) {
            const int d8 = ks * 8;
            const int ra = (qw + g) * FQLD + d8 + t;
            uint32_t a0 = __float_as_uint(Qs[ra]);
            uint32_t a1 = __float_as_uint(Qs[ra + 8 * FQLD]);
            uint32_t a2 = __float_as_uint(Qs[ra + 4]);
            uint32_t a3 = __float_as_uint(Qs[ra + 8 * FQLD + 4]);
            #pragma unroll
            for (int nt = 0; nt < 8; nt++) {
                const int rb = (nt * 8 + g) * FKLD + d8 + t;
                uint32_t b0 = __float_as_uint(Ks[rb]);
                uint32_t b1 = __float_as_uint(Ks[rb + 4]);
                mma_tf32_m16n8k8(s[nt], a0, a1, a2, a3, b0, b1);
            }
        }

        // Online softmax. Rows: g (c0,c1) and g+8 (c2,c3).
        float mt0 = -1e30f, mt1 = -1e30f;
        #pragma unroll
        for (int nt = 0; nt < 8; nt++) {
            mt0 = fmaxf(mt0, fmaxf(s[nt][0], s[nt][1]));
            mt1 = fmaxf(mt1, fmaxf(s[nt][2], s[nt][3]));
        }
        #pragma unroll
        for (int off = 1; off < 4; off <<= 1) {
            mt0 = fmaxf(mt0, __shfl_xor_sync(0xffffffffu, mt0, off));
            mt1 = fmaxf(mt1, __shfl_xor_sync(0xffffffffu, mt1, off));
        }
        const float mn0 = fmaxf(m_i[0], mt0);
        const float mn1 = fmaxf(m_i[1], mt1);
        const float corr0 = __expf(m_i[0] - mn0);
        const float corr1 = __expf(m_i[1] - mn1);
        m_i[0] = mn0; m_i[1] = mn1;

        float ls0 = 0.0f, ls1 = 0.0f;
        #pragma unroll
        for (int nt = 0; nt < 8; nt++) {
            s[nt][0] = __expf(s[nt][0] - mn0);
            s[nt][1] = __expf(s[nt][1] - mn0);
            s[nt][2] = __expf(s[nt][2] - mn1);
            s[nt][3] = __expf(s[nt][3] - mn1);
            ls0 += s[nt][0] + s[nt][1];
            ls1 += s[nt][2] + s[nt][3];
        }
        #pragma unroll
        for (int off = 1; off < 4; off <<= 1) {
            ls0 += __shfl_xor_sync(0xffffffffu, ls0, off);
            ls1 += __shfl_xor_sync(0xffffffffu, ls1, off);
        }
        l_i[0] = l_i[0] * corr0 + ls0;
        l_i[1] = l_i[1] * corr1 + ls1;
        #pragma unroll
        for (int nt = 0; nt < 8; nt++) {
            o[nt][0] *= corr0; o[nt][1] *= corr0;
            o[nt][2] *= corr1; o[nt][3] *= corr1;
        }

        // Stage P (tf32 round) — warp-private rows, float2 stores
        #pragma unroll
        for (int nt = 0; nt < 8; nt++) {
            *(float2*)&Ps[(qw + g) * FPLD + nt * 8 + 2 * t] =
                make_float2(f2tf32f(s[nt][0]), f2tf32f(s[nt][1]));
            *(float2*)&Ps[(qw + g + 8) * FPLD + nt * 8 + 2 * t] =
                make_float2(f2tf32f(s[nt][2]), f2tf32f(s[nt][3]));
        }
        __syncwarp();

        // O += P @ V : 8 n-tiles (d), 8 k-steps (keys)
        #pragma unroll
        for (int ks = 0; ks < 8; ks++) {
            const int key8 = ks * 8;
            const int ra = (qw + g) * FPLD + key8 + t;
            uint32_t a0 = __float_as_uint(Ps[ra]);
            uint32_t a1 = __float_as_uint(Ps[ra + 8 * FPLD]);
            uint32_t a2 = __float_as_uint(Ps[ra + 4]);
            uint32_t a3 = __float_as_uint(Ps[ra + 8 * FPLD + 4]);
            #pragma unroll
            for (int nt = 0; nt < 8; nt++) {
                const int rb = (key8 + t) * FVLD + nt * 8 + g;
                uint32_t b0 = __float_as_uint(Vs[rb]);
                uint32_t b1 = __float_as_uint(Vs[rb + 4 * FVLD]);
                mma_tf32_m16n8k8(o[nt], a0, a1, a2, a3, b0, b1);
            }
        }
    }

    // Write normalized output (float2 per n-tile per row)
    const float inv0 = 1.0f / l_i[0];
    const float inv1 = 1.0f / l_i[1];
    #pragma unroll
    for (int nt = 0; nt < 8; nt++) {
        float* d0 = O + base + (size_t)(q0 + qw + g) * EE + nt * 8 + 2 * t;
        float* d1 = O + base + (size_t)(q0 + qw + g + 8) * EE + nt * 8 + 2 * t;
        *(float2*)d0 = make_float2(o[nt][0] * inv0, o[nt][1] * inv0);
        *(float2*)d1 = make_float2(o[nt][2] * inv1, o[nt][3] * inv1);
    }
}

// ----------------------------------------------------------------------------
extern "C" void kernel_launch(void* const* d_in, const int* in_sizes, int n_in,
                              void* d_out, int out_size)
{
    const float* x  = (const float*)d_in[0];
    const float* Wq = (const float*)d_in[1];
    const float* Wk = (const float*)d_in[2];
    const float* Wv = (const float*)d_in[3];
    const float* Wo = (const float*)d_in[4];
    const float* bo = (const float*)d_in[5];
    float* out = (float*)d_out;

    float *Qp, *Kp, *Vp, *Op, *Ah, *Al, *Wh, *Wl;
    cudaGetSymbolAddress((void**)&Qp, g_Q);
    cudaGetSymbolAddress((void**)&Kp, g_K);
    cudaGetSymbolAddress((void**)&Vp, g_V);
    cudaGetSymbolAddress((void**)&Op, g_O);
    cudaGetSymbolAddress((void**)&Ah, g_Ah);
    cudaGetSymbolAddress((void**)&Al, g_Al);
    cudaGetSymbolAddress((void**)&Wh, g_Wh);
    cudaGetSymbolAddress((void**)&Wl, g_Wl);

    const int nx4 = MM * EE / 4;
    const int nw4 = EE * EE / 4;

    size_t gsmem = 2 * STAGE_F * sizeof(float);   // 143,360 B
    cudaFuncSetAttribute(gemm_tf32x3, cudaFuncAttributeMaxDynamicSharedMemorySize,
                         (int)gsmem);
    size_t fsmem = (128 * FQLD + 64 * FKLD + 64 * FVLD + 128 * FPLD) * sizeof(float);
    cudaFuncSetAttribute(flash_mma, cudaFuncAttributeMaxDynamicSharedMemorySize,
                         (int)fsmem);

    dim3 gg(EE / 128, MM / 128);   // (8, 64)
    dim3 ga(LL / 128, HH, BB);     // (16, 16, 4)

    // Split x once (used by 3 projections)
    split_tf32<<<(nx4 + 255) / 256, 256>>>((const float4*)x, (float4*)Ah, (float4*)Al, nx4);

    // Q/K/V projections: split weight, then gemm (stream-ordered)
    split_tf32<<<(nw4 + 255) / 256, 256>>>((const float4*)Wq, (float4*)Wh, (float4*)Wl, nw4);
    gemm_tf32x3<<<gg, 256, gsmem>>>(Ah, Al, Wh, Wl, nullptr, Qp, MM, EE, EE);
    split_tf32<<<(nw4 + 255) / 256, 256>>>((const float4*)Wk, (float4*)Wh, (float4*)Wl, nw4);
    gemm_tf32x3<<<gg, 256, gsmem>>>(Ah, Al, Wh, Wl, nullptr, Kp, MM, EE, EE);
    split_tf32<<<(nw4 + 255) / 256, 256>>>((const float4*)Wv, (float4*)Wh, (float4*)Wl, nw4);
    gemm_tf32x3<<<gg, 256, gsmem>>>(Ah, Al, Wh, Wl, nullptr, Vp, MM, EE, EE);

    // Attention (tensor cores)
    flash_mma<<<ga, 256, fsmem>>>(Qp, Kp, Vp, Op);

    // Output projection: split O (reuse Ah/Al) + Wo, gemm with bias
    split_tf32<<<(nx4 + 255) / 256, 256>>>((const float4*)Op, (float4*)Ah, (float4*)Al, nx4);
    split_tf32<<<(nw4 + 255) / 256, 256>>>((const float4*)Wo, (float4*)Wh, (float4*)Wl, nw4);
    gemm_tf32x3<<<gg, 256, gsmem>>>(Ah, Al, Wh, Wl, bo, out, MM, EE, EE);
}

// round 5
// speedup vs baseline: 3.3874x; 1.3975x over previous
#include <cuda_runtime.h>
#include <cuda_bf16.h>
#include <cstdint>

// Problem constants
#define BB 4
#define LL 2048
#define EE 1024
#define HH 16
#define DD 64
#define MM (BB * LL)   // 8192 rows

// Scratch (allocation-free rule: __device__ globals)
__device__ float g_Q[MM * EE];
__device__ float g_K[MM * EE];
__device__ float g_V[MM * EE];
__device__ float g_O[MM * EE];
__device__ __nv_bfloat16 g_Ah[MM * EE];
__device__ __nv_bfloat16 g_Al[MM * EE];
__device__ __nv_bfloat16 g_Wh[EE * EE];
__device__ __nv_bfloat16 g_Wl[EE * EE];

// ----------------------------------------------------------------------------
// helpers
// ----------------------------------------------------------------------------
__device__ __forceinline__ uint32_t f2tf32(float a) {
    uint32_t r;
    asm("cvt.rna.tf32.f32 %0, %1;" : "=r"(r) : "f"(a));
    return r;
}
__device__ __forceinline__ float f2tf32f(float a) {
    return __uint_as_float(f2tf32(a));
}

__device__ __forceinline__ void mma_tf32_m16n8k8(
    float d[4], uint32_t a0, uint32_t a1, uint32_t a2, uint32_t a3,
    uint32_t b0, uint32_t b1)
{
    asm volatile(
        "mma.sync.aligned.m16n8k8.row.col.f32.tf32.tf32.f32 "
        "{%0,%1,%2,%3}, {%4,%5,%6,%7}, {%8,%9}, {%0,%1,%2,%3};"
        : "+f"(d[0]), "+f"(d[1]), "+f"(d[2]), "+f"(d[3])
        : "r"(a0), "r"(a1), "r"(a2), "r"(a3), "r"(b0), "r"(b1));
}

__device__ __forceinline__ void mma_bf16_m16n8k16(
    float d[4], uint32_t a0, uint32_t a1, uint32_t a2, uint32_t a3,
    uint32_t b0, uint32_t b1)
{
    asm volatile(
        "mma.sync.aligned.m16n8k16.row.col.f32.bf16.bf16.f32 "
        "{%0,%1,%2,%3}, {%4,%5,%6,%7}, {%8,%9}, {%0,%1,%2,%3};"
        : "+f"(d[0]), "+f"(d[1]), "+f"(d[2]), "+f"(d[3])
        : "r"(a0), "r"(a1), "r"(a2), "r"(a3), "r"(b0), "r"(b1));
}

__device__ __forceinline__ void cp16(uint32_t smem_dst, const void* gsrc) {
    asm volatile("cp.async.cg.shared.global [%0], [%1], 16;\n"
                 :: "r"(smem_dst), "l"(gsrc));
}
__device__ __forceinline__ void cp_commit() {
    asm volatile("cp.async.commit_group;\n");
}
template <int N> __device__ __forceinline__ void cp_wait() {
    asm volatile("cp.async.wait_group %0;\n" :: "n"(N));
}

// ----------------------------------------------------------------------------
// Elementwise split fp32 -> (bf16 hi, bf16 lo). n2 = element count / 2.
// ----------------------------------------------------------------------------
__global__ __launch_bounds__(256) void split_bf16(
    const float2* __restrict__ in, __nv_bfloat162* __restrict__ hi,
    __nv_bfloat162* __restrict__ lo, int n2)
{
    int i = blockIdx.x * blockDim.x + threadIdx.x;
    if (i >= n2) return;
    float2 v = in[i];
    __nv_bfloat16 hx = __float2bfloat16(v.x);
    __nv_bfloat16 hy = __float2bfloat16(v.y);
    __nv_bfloat16 lx = __float2bfloat16(v.x - __bfloat162float(hx));
    __nv_bfloat16 ly = __float2bfloat16(v.y - __bfloat162float(hy));
    hi[i] = __nv_bfloat162{hx, hy};
    lo[i] = __nv_bfloat162{lx, ly};
}

// ----------------------------------------------------------------------------
// Split + transpose: W fp32 [K][N] -> hi/lo bf16 [N][K]. 32x32 tiles, 256 thr.
// ----------------------------------------------------------------------------
__global__ __launch_bounds__(256) void split_bf16_T(
    const float* __restrict__ in, __nv_bfloat16* __restrict__ hi,
    __nv_bfloat16* __restrict__ lo, int K, int N)
{
    __shared__ float tile[32][33];
    const int k0 = blockIdx.y * 32;
    const int n0 = blockIdx.x * 32;
    const int tx = threadIdx.x & 31;
    const int ty = threadIdx.x >> 5;   // 0..7

    #pragma unroll
    for (int p = 0; p < 4; p++)
        tile[ty + p * 8][tx] = in[(size_t)(k0 + ty + p * 8) * N + n0 + tx];
    __syncthreads();

    #pragma unroll
    for (int p = 0; p < 4; p++) {
        const int n = n0 + ty + p * 8;
        float v = tile[tx][ty + p * 8];
        __nv_bfloat16 h = __float2bfloat16(v);
        __nv_bfloat16 l = __float2bfloat16(v - __bfloat162float(h));
        hi[(size_t)n * K + k0 + tx] = h;
        lo[(size_t)n * K + k0 + tx] = l;
    }
}

// ----------------------------------------------------------------------------
// bf16x3 GEMM, pre-split operands, 2-stage cp.async pipeline.
// C[M,N] = (Ah+Al)[M,K] @ (Bh+Bl)^T  where Bt is [N][K] bf16 (pre-transposed).
// Block 128x128, BK=32; 8 warps (2m x 4n), warp tile 64x32, mma m16n8k16.
// ----------------------------------------------------------------------------
#define GLDB 40    // smem row stride in bf16 (32 + 8 pad)
#define STAGE_B (4 * 128 * GLDB)   // bf16 elems/stage (Ah,Al,Bh,Bl) = 20480

__global__ __launch_bounds__(256, 1) void gemm_bf16x3(
    const __nv_bfloat16* __restrict__ Ah, const __nv_bfloat16* __restrict__ Al,
    const __nv_bfloat16* __restrict__ Bh, const __nv_bfloat16* __restrict__ Bl,
    const float* __restrict__ bias, float* __restrict__ C,
    int M, int N, int K)
{
    extern __shared__ __nv_bfloat16 gsmb[];
    const uint32_t smbase = (uint32_t)__cvta_generic_to_shared(gsmb);

    const int tid  = threadIdx.x;
    const int lane = tid & 31;
    const int wid  = tid >> 5;
    const int wm   = (wid >> 2) * 64;
    const int wn   = (wid & 3) * 32;
    const int g    = lane >> 2;
    const int t    = lane & 3;

    const int m0 = blockIdx.y * 128;
    const int n0 = blockIdx.x * 128;

    float acc[4][4][4];
    #pragma unroll
    for (int i = 0; i < 4; i++)
        #pragma unroll
        for (int j = 0; j < 4; j++)
            #pragma unroll
            for (int r = 0; r < 4; r++) acc[i][j][r] = 0.0f;

    // loader indices: 128 rows x 32 bf16 (64B) per array -> 4 chunks/row
    const int lr = tid >> 2;          // 0..63 (2 passes of 64 rows)
    const int lc = (tid & 3) * 8;     // bf16 col of 16B chunk

    auto load_stage = [&](int stage, int k0) {
        const uint32_t s0 = smbase + stage * STAGE_B * 2;
        const uint32_t aH = s0;
        const uint32_t aL = s0 + 128 * GLDB * 2;
        const uint32_t bH = s0 + 2 * 128 * GLDB * 2;
        const uint32_t bL = bH + 128 * GLDB * 2;
        #pragma unroll
        for (int p = 0; p < 2; p++) {
            const int r = lr + p * 64;
            const uint32_t so = (r * GLDB + lc) * 2;
            const size_t ga = (size_t)(m0 + r) * K + k0 + lc;
            cp16(aH + so, Ah + ga);
            cp16(aL + so, Al + ga);
            const size_t gb = (size_t)(n0 + r) * K + k0 + lc;
            cp16(bH + so, Bh + gb);
            cp16(bL + so, Bl + gb);
        }
        cp_commit();
    };

    load_stage(0, 0);

    const int ntiles = K / 32;
    for (int kt = 0; kt < ntiles; kt++) {
        if (kt + 1 < ntiles) {
            load_stage((kt + 1) & 1, (kt + 1) * 32);
            cp_wait<1>();
        } else {
            cp_wait<0>();
        }
        __syncthreads();

        const __nv_bfloat16* AsH = gsmb + (kt & 1) * STAGE_B;
        const __nv_bfloat16* AsL = AsH + 128 * GLDB;
        const __nv_bfloat16* BsH = AsL + 128 * GLDB;
        const __nv_bfloat16* BsL = BsH + 128 * GLDB;

        #pragma unroll
        for (int ks = 0; ks < 2; ks++) {
            const int kk = ks * 16 + 2 * t;
            uint32_t ah[4][4], al[4][4];
            #pragma unroll
            for (int mt = 0; mt < 4; mt++) {
                const int ra = (wm + mt * 16 + g) * GLDB + kk;
                ah[mt][0] = *(const uint32_t*)&AsH[ra];
                ah[mt][1] = *(const uint32_t*)&AsH[ra + 8 * GLDB];
                ah[mt][2] = *(const uint32_t*)&AsH[ra + 8];
                ah[mt][3] = *(const uint32_t*)&AsH[ra + 8 * GLDB + 8];
                al[mt][0] = *(const uint32_t*)&AsL[ra];
                al[mt][1] = *(const uint32_t*)&AsL[ra + 8 * GLDB];
                al[mt][2] = *(const uint32_t*)&AsL[ra + 8];
                al[mt][3] = *(const uint32_t*)&AsL[ra + 8 * GLDB + 8];
            }
            uint32_t bh[4][2], bl[4][2];
            #pragma unroll
            for (int nt = 0; nt < 4; nt++) {
                const int rb = (wn + nt * 8 + g) * GLDB + kk;
                bh[nt][0] = *(const uint32_t*)&BsH[rb];
                bh[nt][1] = *(const uint32_t*)&BsH[rb + 8];
                bl[nt][0] = *(const uint32_t*)&BsL[rb];
                bl[nt][1] = *(const uint32_t*)&BsL[rb + 8];
            }
            #pragma unroll
            for (int mt = 0; mt < 4; mt++)
                #pragma unroll
                for (int nt = 0; nt < 4; nt++) {
                    mma_bf16_m16n8k16(acc[mt][nt], al[mt][0], al[mt][1], al[mt][2], al[mt][3],
                                      bh[nt][0], bh[nt][1]);
                    mma_bf16_m16n8k16(acc[mt][nt], ah[mt][0], ah[mt][1], ah[mt][2], ah[mt][3],
                                      bl[nt][0], bl[nt][1]);
                    mma_bf16_m16n8k16(acc[mt][nt], ah[mt][0], ah[mt][1], ah[mt][2], ah[mt][3],
                                      bh[nt][0], bh[nt][1]);
                }
        }
        __syncthreads();
    }

    // Epilogue
    #pragma unroll
    for (int mt = 0; mt < 4; mt++) {
        const int r0 = m0 + wm + mt * 16 + g;
        #pragma unroll
        for (int nt = 0; nt < 4; nt++) {
            const int c = n0 + wn + nt * 8 + 2 * t;
            float b0 = bias ? bias[c]     : 0.0f;
            float b1 = bias ? bias[c + 1] : 0.0f;
            *(float2*)&C[(size_t)r0 * N + c] =
                make_float2(acc[mt][nt][0] + b0, acc[mt][nt][1] + b1);
            *(float2*)&C[(size_t)(r0 + 8) * N + c] =
                make_float2(acc[mt][nt][2] + b0, acc[mt][nt][3] + b1);
        }
    }
}

// ----------------------------------------------------------------------------
// Flash attention, tf32 tensor-core MMAs, cp.async double-buffered K/V.
// 128 q-rows/block, 64-key tiles; 8 warps each own 16 q-rows.
// K/V kept raw fp32 in smem; tf32 MMA truncates mantissa implicitly.
// ----------------------------------------------------------------------------
#define FQLD 68
#define FKLD 68
#define FVLD 72
#define FPLD 72

__global__ __launch_bounds__(256, 1) void flash_mma(
    const float* __restrict__ Q, const float* __restrict__ Kg,
    const float* __restrict__ Vg, float* __restrict__ O)
{
    extern __shared__ float sm[];
    float* Qs  = sm;                         // [128][FQLD]
    float* Ksb = Qs + 128 * FQLD;            // 2 x [64][FKLD]
    float* Vsb = Ksb + 2 * 64 * FKLD;        // 2 x [64][FVLD]
    float* Ps  = Vsb + 2 * 64 * FVLD;        // [128][FPLD]
    const uint32_t smKs = (uint32_t)__cvta_generic_to_shared(Ksb);
    const uint32_t smVs = (uint32_t)__cvta_generic_to_shared(Vsb);

    const int tid  = threadIdx.x;
    const int lane = tid & 31;
    const int wid  = tid >> 5;
    const int g    = lane >> 2;
    const int t    = lane & 3;
    const int qw   = wid * 16;

    const int q0 = blockIdx.x * 128;
    const int h  = blockIdx.y;
    const int b  = blockIdx.z;
    const float scale = 0.03125f;            // 1/sqrt(1024)
    const size_t base = (size_t)b * LL * EE + (size_t)h * DD;

    auto load_kv = [&](int buf, int kt) {
        const int r = tid >> 2;              // 0..63
        const float* ksrc = Kg + base + (size_t)(kt + r) * EE;
        const float* vsrc = Vg + base + (size_t)(kt + r) * EE;
        const uint32_t kdst = smKs + (buf * 64 * FKLD + r * FKLD) * 4;
        const uint32_t vdst = smVs + (buf * 64 * FVLD + r * FVLD) * 4;
        #pragma unroll
        for (int u = 0; u < 4; u++) {
            const int c = ((tid & 3) + u * 4) * 4;   // float col
            cp16(kdst + c * 4, ksrc + c);
            cp16(vdst + c * 4, vsrc + c);
        }
        cp_commit();
    };

    load_kv(0, 0);

    // Load Q tile (scale + tf32 round), q-major
    {
        const int r  = tid >> 1;
        const int c0 = (tid & 1) * 32;
        const float* src = Q + base + (size_t)(q0 + r) * EE + c0;
        #pragma unroll
        for (int u = 0; u < 8; u++) {
            float4 v = *(const float4*)(src + u * 4);
            Qs[r * FQLD + c0 + u * 4 + 0] = f2tf32f(v.x * scale);
            Qs[r * FQLD + c0 + u * 4 + 1] = f2tf32f(v.y * scale);
            Qs[r * FQLD + c0 + u * 4 + 2] = f2tf32f(v.z * scale);
            Qs[r * FQLD + c0 + u * 4 + 3] = f2tf32f(v.w * scale);
        }
    }

    float m_i[2] = {-1e30f, -1e30f};
    float l_i[2] = {0.0f, 0.0f};
    float o[8][4];
    #pragma unroll
    for (int nt = 0; nt < 8; nt++)
        #pragma unroll
        for (int r = 0; r < 4; r++) o[nt][r] = 0.0f;

    const int NT = LL / 64;
    for (int it = 0; it < NT; it++) {
        cp_wait<0>();
        __syncthreads();
        if (it + 1 < NT) load_kv((it + 1) & 1, (it + 1) * 64);

        const float* Ks = Ksb + (it & 1) * 64 * FKLD;
        const float* Vs = Vsb + (it & 1) * 64 * FVLD;

        // S = Q @ K^T
        float s[8][4];
        #pragma unroll
        for (int nt = 0; nt < 8; nt++)
            #pragma unroll
            for (int r = 0; r < 4; r++) s[nt][r] = 0.0f;

        #pragma unroll
        for (int ks = 0; ks < 8; ks++) {
            const int d8 = ks * 8;
            const int ra = (qw + g) * FQLD + d8 + t;
            uint32_t a0 = __float_as_uint(Qs[ra]);
            uint32_t a1 = __float_as_uint(Qs[ra + 8 * FQLD]);
            uint32_t a2 = __float_as_uint(Qs[ra + 4]);
            uint32_t a3 = __float_as_uint(Qs[ra + 8 * FQLD + 4]);
            #pragma unroll
            for (int nt = 0; nt < 8; nt++) {
                const int rb = (nt * 8 + g) * FKLD + d8 + t;
                uint32_t b0 = __float_as_uint(Ks[rb]);
                uint32_t b1 = __float_as_uint(Ks[rb + 4]);
                mma_tf32_m16n8k8(s[nt], a0, a1, a2, a3, b0, b1);
            }
        }

        // Online softmax. Rows: g (c0,c1) and g+8 (c2,c3).
        float mt0 = -1e30f, mt1 = -1e30f;
        #pragma unroll
        for (int nt = 0; nt < 8; nt++) {
            mt0 = fmaxf(mt0, fmaxf(s[nt][0], s[nt][1]));
            mt1 = fmaxf(mt1, fmaxf(s[nt][2], s[nt][3]));
        }
        #pragma unroll
        for (int off = 1; off < 4; off <<= 1) {
            mt0 = fmaxf(mt0, __shfl_xor_sync(0xffffffffu, mt0, off));
            mt1 = fmaxf(mt1, __shfl_xor_sync(0xffffffffu, mt1, off));
        }
        const float mn0 = fmaxf(m_i[0], mt0);
        const float mn1 = fmaxf(m_i[1], mt1);
        const float corr0 = __expf(m_i[0] - mn0);
        const float corr1 = __expf(m_i[1] - mn1);
        m_i[0] = mn0; m_i[1] = mn1;

        float ls0 = 0.0f, ls1 = 0.0f;
        #pragma unroll
        for (int nt = 0; nt < 8; nt++) {
            s[nt][0] = __expf(s[nt][0] - mn0);
            s[nt][1] = __expf(s[nt][1] - mn0);
            s[nt][2] = __expf(s[nt][2] - mn1);
            s[nt][3] = __expf(s[nt][3] - mn1);
            ls0 += s[nt][0] + s[nt][1];
            ls1 += s[nt][2] + s[nt][3];
        }
        #pragma unroll
        for (int off = 1; off < 4; off <<= 1) {
            ls0 += __shfl_xor_sync(0xffffffffu, ls0, off);
            ls1 += __shfl_xor_sync(0xffffffffu, ls1, off);
        }
        l_i[0] = l_i[0] * corr0 + ls0;
        l_i[1] = l_i[1] * corr1 + ls1;
        #pragma unroll
        for (int nt = 0; nt < 8; nt++) {
            o[nt][0] *= corr0; o[nt][1] *= corr0;
            o[nt][2] *= corr1; o[nt][3] *= corr1;
        }

        // Stage P (tf32 round) — warp-private rows
        #pragma unroll
        for (int nt = 0; nt < 8; nt++) {
            *(float2*)&Ps[(qw + g) * FPLD + nt * 8 + 2 * t] =
                make_float2(f2tf32f(s[nt][0]), f2tf32f(s[nt][1]));
            *(float2*)&Ps[(qw + g + 8) * FPLD + nt * 8 + 2 * t] =
                make_float2(f2tf32f(s[nt][2]), f2tf32f(s[nt][3]));
        }
        __syncwarp();

        // O += P @ V
        #pragma unroll
        for (int ks = 0; ks < 8; ks++) {
            const int key8 = ks * 8;
            const int ra = (qw + g) * FPLD + key8 + t;
            uint32_t a0 = __float_as_uint(Ps[ra]);
            uint32_t a1 = __float_as_uint(Ps[ra + 8 * FPLD]);
            uint32_t a2 = __float_as_uint(Ps[ra + 4]);
            uint32_t a3 = __float_as_uint(Ps[ra + 8 * FPLD + 4]);
            #pragma unroll
            for (int nt = 0; nt < 8; nt++) {
                const int rb = (key8 + t) * FVLD + nt * 8 + g;
                uint32_t b0 = __float_as_uint(Vs[rb]);
                uint32_t b1 = __float_as_uint(Vs[rb + 4 * FVLD]);
                mma_tf32_m16n8k8(o[nt], a0, a1, a2, a3, b0, b1);
            }
        }
        __syncthreads();
    }

    const float inv0 = 1.0f / l_i[0];
    const float inv1 = 1.0f / l_i[1];
    #pragma unroll
    for (int nt = 0; nt < 8; nt++) {
        float* d0 = O + base + (size_t)(q0 + qw + g) * EE + nt * 8 + 2 * t;
        float* d1 = O + base + (size_t)(q0 + qw + g + 8) * EE + nt * 8 + 2 * t;
        *(float2*)d0 = make_float2(o[nt][0] * inv0, o[nt][1] * inv0);
        *(float2*)d1 = make_float2(o[nt][2] * inv1, o[nt][3] * inv1);
    }
}

// ----------------------------------------------------------------------------
extern "C" void kernel_launch(void* const* d_in, const int* in_sizes, int n_in,
                              void* d_out, int out_size)
{
    const float* x  = (const float*)d_in[0];
    const float* Wq = (const float*)d_in[1];
    const float* Wk = (const float*)d_in[2];
    const float* Wv = (const float*)d_in[3];
    const float* Wo = (const float*)d_in[4];
    const float* bo = (const float*)d_in[5];
    float* out = (float*)d_out;

    float *Qp, *Kp, *Vp, *Op;
    __nv_bfloat16 *Ah, *Al, *Wh, *Wl;
    cudaGetSymbolAddress((void**)&Qp, g_Q);
    cudaGetSymbolAddress((void**)&Kp, g_K);
    cudaGetSymbolAddress((void**)&Vp, g_V);
    cudaGetSymbolAddress((void**)&Op, g_O);
    cudaGetSymbolAddress((void**)&Ah, g_Ah);
    cudaGetSymbolAddress((void**)&Al, g_Al);
    cudaGetSymbolAddress((void**)&Wh, g_Wh);
    cudaGetSymbolAddress((void**)&Wl, g_Wl);

    const int nx2 = MM * EE / 2;

    size_t gsmem = 2 * STAGE_B * sizeof(__nv_bfloat16);   // 81,920 B
    cudaFuncSetAttribute(gemm_bf16x3, cudaFuncAttributeMaxDynamicSharedMemorySize,
                         (int)gsmem);
    size_t fsmem = (128 * FQLD + 2 * 64 * FKLD + 2 * 64 * FVLD + 128 * FPLD)
                   * sizeof(float);                        // 143,360 B
    cudaFuncSetAttribute(flash_mma, cudaFuncAttributeMaxDynamicSharedMemorySize,
                         (int)fsmem);

    dim3 gg(EE / 128, MM / 128);        // (8, 64)
    dim3 ga(LL / 128, HH, BB);          // (16, 16, 4)
    dim3 gt(EE / 32, EE / 32);          // (32, 32) transpose-split grid

    // Split x once (used by 3 projections)
    split_bf16<<<(nx2 + 255) / 256, 256>>>((const float2*)x,
        (__nv_bfloat162*)Ah, (__nv_bfloat162*)Al, nx2);

    // Q/K/V projections: split+transpose weight, then gemm
    split_bf16_T<<<gt, 256>>>(Wq, Wh, Wl, EE, EE);
    gemm_bf16x3<<<gg, 256, gsmem>>>(Ah, Al, Wh, Wl, nullptr, Qp, MM, EE, EE);
    split_bf16_T<<<gt, 256>>>(Wk, Wh, Wl, EE, EE);
    gemm_bf16x3<<<gg, 256, gsmem>>>(Ah, Al, Wh, Wl, nullptr, Kp, MM, EE, EE);
    split_bf16_T<<<gt, 256>>>(Wv, Wh, Wl, EE, EE);
    gemm_bf16x3<<<gg, 256, gsmem>>>(Ah, Al, Wh, Wl, nullptr, Vp, MM, EE, EE);

    // Attention (tensor cores, pipelined K/V)
    flash_mma<<<ga, 256, fsmem>>>(Qp, Kp, Vp, Op);

    // Output projection: split O + Wo, gemm with bias
    split_bf16<<<(nx2 + 255) / 256, 256>>>((const float2*)Op,
        (__nv_bfloat162*)Ah, (__nv_bfloat162*)Al, nx2);
    split_bf16_T<<<gt, 256>>>(Wo, Wh, Wl, EE, EE);
    gemm_bf16x3<<<gg, 256, gsmem>>>(Ah, Al, Wh, Wl, bo, out, MM, EE, EE);
}